// round 9
// baseline (speedup 1.0000x reference)
#include <cuda_runtime.h>
#include <math.h>

#define C_IN   64
#define FD     8
#define OUTC   9
#define KW     5
#define HEIGHT 4096
#define BATCH  32
#define NTOK   (BATCH * HEIGHT)      // 131072 tokens (b,h)
#define HALF   36
#define MIN_EIG 0.001f
#define NSWEEP 4

// SoA scratch: sigma[e][token]
__device__ float g_sigma[HALF * NTOK];
// Winograd-transformed p-conv weights: [c][o][4] packed pairs of
// (G~0,G~1)(G~2,G~3)(G~4,G~5)(G~6, g4); G~i = g(a_i)/N_i
__device__ unsigned long long g_gt[C_IN * OUTC * 4];
__device__ float g_wnf[C_IN];

typedef unsigned long long ull;

__device__ __forceinline__ ull pk(float lo, float hi) {
    ull r; asm("mov.b64 %0, {%1, %2};" : "=l"(r) : "f"(lo), "f"(hi)); return r;
}
__device__ __forceinline__ void upk(ull v, float& lo, float& hi) {
    asm("mov.b64 {%0, %1}, %2;" : "=f"(lo), "=f"(hi) : "l"(v));
}
__device__ __forceinline__ ull fma2(ull a, ull b, ull c) {
    ull d; asm("fma.rn.f32x2 %0, %1, %2, %3;" : "=l"(d) : "l"(a), "l"(b), "l"(c)); return d;
}
__device__ __forceinline__ ull mul2(ull a, ull b) {
    ull d; asm("mul.rn.f32x2 %0, %1, %2;" : "=l"(d) : "l"(a), "l"(b)); return d;
}
__device__ __forceinline__ float softplus(float v) {
    return v > 20.0f ? v : log1pf(expf(v));
}

// ---------------------------------------------------------------------------
// Setup: Winograd g-side constants, computed numerically (double precision).
// Points a = {0, 1, -1, 2, -2, 1/2, -1/2}, plus infinity (index 7).
// y_w = sum_i a_i^w * (g(a_i)/N_i) * dtil_i  +  [w==3] * g_4 * (pi . d)
// ---------------------------------------------------------------------------
__global__ void wprep_kernel(const float* __restrict__ wn,
                             const float* __restrict__ wp)
{
    const int i = blockIdx.x * 128 + threadIdx.x;
    if (i < C_IN) g_wnf[i] = wn[i];
    if (i >= OUTC * C_IN) return;
    const int o = i / C_IN, c = i % C_IN;

    const double a[7] = {0.0, 1.0, -1.0, 2.0, -2.0, 0.5, -0.5};
    double g[5];
#pragma unroll
    for (int k = 0; k < 5; k++) g[k] = (double)wp[(o * C_IN + c) * KW + k];

    float Gt[8];
#pragma unroll
    for (int ii = 0; ii < 7; ii++) {
        // Horner: g(a_ii)
        double ge = g[4];
#pragma unroll
        for (int k = 3; k >= 0; k--) ge = ge * a[ii] + g[k];
        double N = 1.0;
#pragma unroll
        for (int j = 0; j < 7; j++) if (j != ii) N *= (a[ii] - a[j]);
        Gt[ii] = (float)(ge / N);
    }
    Gt[7] = (float)g[4];

    ull* dst = g_gt + (c * OUTC + o) * 4;
    dst[0] = pk(Gt[0], Gt[1]);
    dst[1] = pk(Gt[2], Gt[3]);
    dst[2] = pk(Gt[4], Gt[5]);
    dst[3] = pk(Gt[6], Gt[7]);
}

// ---------------------------------------------------------------------------
// Kernel 1: Winograd F(4,5) p-conv + scalar 1x1 conv (loc).
// One thread = one token. Per channel:
//   8 data functionals (~26 scalar FMA, shared by all 9 outputs)
//   9 x 4 fma2 products accumulated over channels
//   8 scalar FMA for loc
// Output transform (A^T) + softplus once per token in epilogue.
// ---------------------------------------------------------------------------
__global__ void __launch_bounds__(128) conv_kernel(
    const float* __restrict__ x,   // [B, C_IN, H, FD]
    const float* __restrict__ bn,  // [1]
    const float* __restrict__ bp,  // [OUTC]
    float* __restrict__ out_loc)   // [NTOK, FD]
{
    __shared__ ull  s_gt[C_IN * OUTC * 4];   // 18 KB
    __shared__ float s_wn[C_IN];
    __shared__ float s_b[OUTC + 1];

    const int t = threadIdx.x;
#pragma unroll
    for (int i = 0; i < (C_IN * OUTC * 4) / 128; i++)
        s_gt[t + 128 * i] = g_gt[t + 128 * i];
    if (t < C_IN) s_wn[t] = g_wnf[t];
    if (t < OUTC) s_b[t] = bp[t];
    if (t == 0)   s_b[OUTC] = bn[0];
    __syncthreads();

    const int tok = blockIdx.x * 128 + t;
    const int b = tok >> 12;           // H = 4096
    const int h = tok & (HEIGHT - 1);
    const float* xb = x + (size_t)b * (C_IN * HEIGHT * FD) + (size_t)h * FD;

    ull acc[OUTC * 4];                 // acc[o*4+p] = (P_{2p}, P_{2p+1})
    float accL[FD];
#pragma unroll
    for (int e = 0; e < OUTC * 4; e++) acc[e] = 0ULL;
#pragma unroll
    for (int j = 0; j < FD; j++) accL[j] = 0.0f;

    const float4* p0 = (const float4*)xb;
    float4 u = p0[0];
    float4 v = p0[1];

#pragma unroll 4
    for (int c = 0; c < C_IN; c++) {
        float4 nu, nv;
        if (c < C_IN - 1) {
            const float4* pn = (const float4*)(xb + (size_t)(c + 1) * (HEIGHT * FD));
            nu = pn[0]; nv = pn[1];
        }
        const float d0 = u.x, d1 = u.y, d2 = u.z, d3 = u.w;
        const float d4 = v.x, d5 = v.y, d6 = v.z, d7 = v.w;

        // loc (scalar)
        {
            const float wc = s_wn[c];
            accL[0] = fmaf(wc, d0, accL[0]); accL[1] = fmaf(wc, d1, accL[1]);
            accL[2] = fmaf(wc, d2, accL[2]); accL[3] = fmaf(wc, d3, accL[3]);
            accL[4] = fmaf(wc, d4, accL[4]); accL[5] = fmaf(wc, d5, accL[5]);
            accL[6] = fmaf(wc, d6, accL[6]); accL[7] = fmaf(wc, d7, accL[7]);
        }

        // Winograd data functionals (tile-8 points 0,+-1,+-2,+-1/2,inf)
        const float E1 = fmaf(-4.25f, d4, d2 + d6);
        const float O1 = fmaf(-4.25f, d3, d1 + d5);
        const float E2 = fmaf(0.25f, d2, fmaf(-1.25f, d4, d6));
        const float O2 = fmaf(0.5f,  d1, fmaf(-2.5f,  d3, 2.0f * d5));
        const float E3 = fmaf(4.0f,  d2, fmaf(-5.0f,  d4, d6));
        const float O3 = fmaf(2.0f,  d1, fmaf(-2.5f,  d3, 0.5f * d5));
        const float F0 = fmaf(5.25f, d2 - d4, d6 - d0);   // point 0
        const float F1 = E1 + O1;                          // +1
        const float F2 = E1 - O1;                          // -1
        const float F3 = E2 + O2;                          // +2
        const float F4 = E2 - O2;                          // -2
        const float F5 = E3 + O3;                          // +1/2
        const float F6 = E3 - O3;                          // -1/2
        const float F7 = fmaf(5.25f, d3 - d5, d7 - d1);    // pi (inf)

        const ull X01 = pk(F0, F1);
        const ull X23 = pk(F2, F3);
        const ull X45 = pk(F4, F5);
        const ull X67 = pk(F6, F7);

        const ull* gc = s_gt + c * (OUTC * 4);
#pragma unroll
        for (int o = 0; o < OUTC; o++) {
            ulonglong2 wA = *(const ulonglong2*)(gc + o * 4);
            ulonglong2 wB = *(const ulonglong2*)(gc + o * 4 + 2);
            acc[o * 4 + 0] = fma2(X01, wA.x, acc[o * 4 + 0]);
            acc[o * 4 + 1] = fma2(X23, wA.y, acc[o * 4 + 1]);
            acc[o * 4 + 2] = fma2(X45, wB.x, acc[o * 4 + 2]);
            acc[o * 4 + 3] = fma2(X67, wB.y, acc[o * 4 + 3]);
        }
        u = nu; v = nv;
    }

    // ---- epilogue: output transform A^T + softplus ----
#pragma unroll
    for (int o = 0; o < OUTC; o++) {
        float P0, P1, P2, P3, P4, P5, P6, P7;
        upk(acc[o * 4 + 0], P0, P1);
        upk(acc[o * 4 + 1], P2, P3);
        upk(acc[o * 4 + 2], P4, P5);
        upk(acc[o * 4 + 3], P6, P7);
        const float S1 = P1 + P2, D1 = P1 - P2;
        const float S2 = P3 + P4, D2 = P3 - P4;
        const float S3 = P5 + P6, D3 = P5 - P6;
        const float y0 = P0 + S1 + S2 + S3;
        const float y1 = fmaf(2.0f, D2, fmaf(0.5f,   D3, D1));
        const float y2 = fmaf(4.0f, S2, fmaf(0.25f,  S3, S1));
        const float y3 = fmaf(8.0f, D2, fmaf(0.125f, D3, D1)) + P7;
        const float be = s_b[o];
        g_sigma[(size_t)(o * 4 + 0) * NTOK + tok] = softplus(y0 + be);
        g_sigma[(size_t)(o * 4 + 1) * NTOK + tok] = softplus(y1 + be);
        g_sigma[(size_t)(o * 4 + 2) * NTOK + tok] = softplus(y2 + be);
        g_sigma[(size_t)(o * 4 + 3) * NTOK + tok] = softplus(y3 + be);
    }

    {
        const float bnv = s_b[OUTC];
        float r[8];
#pragma unroll
        for (int j = 0; j < FD; j++) r[j] = softplus(accL[j] + bnv);
        float4* lp = (float4*)(out_loc + (size_t)tok * FD);
        lp[0] = make_float4(r[0], r[1], r[2], r[3]);
        lp[1] = make_float4(r[4], r[5], r[6], r[7]);
    }
}

// ---------------------------------------------------------------------------
// Kernel 2: batched 8x8 symmetric eigh, fixed-sweep cyclic Jacobi.
// (R5 version verbatim: A triangle, packed V, W materialized, no reg cap.)
// ---------------------------------------------------------------------------
#define TI(i,j) ((i) <= (j) ? ((i)*(17-(i)))/2 + ((j)-(i)) \
                            : ((j)*(17-(j)))/2 + ((i)-(j)))
#define AT(i,j) Au[TI(i,j)]

__global__ void __launch_bounds__(128) eigh_kernel(float* __restrict__ out_pd)
{
    const int tok = blockIdx.x * 128 + threadIdx.x;

    float Au[HALF];
#pragma unroll
    for (int e = 0; e < HALF; e++) Au[e] = g_sigma[(size_t)e * NTOK + tok];

    // V packed as row-pairs: Vp[col][jp] = ( V[2jp][col], V[2jp+1][col] )
    ull Vp[8][4];
#pragma unroll
    for (int c = 0; c < 8; c++)
#pragma unroll
        for (int jp = 0; jp < 4; jp++)
            Vp[c][jp] = pk((2 * jp == c) ? 1.0f : 0.0f,
                           (2 * jp + 1 == c) ? 1.0f : 0.0f);

#pragma unroll 1
    for (int sweep = 0; sweep < NSWEEP; sweep++) {
#pragma unroll
        for (int p = 0; p < 7; p++) {
#pragma unroll
            for (int q = p + 1; q < 8; q++) {
                float apq = AT(p, q);
                float app = AT(p, p);
                float aqq = AT(q, q);
                float tau = (aqq - app);
                tau += copysignf(1e-18f, tau);          // degenerate-safe
                float r2    = fmaf(tau, tau, 4.0f * apq * apq);
                float inv_r = rsqrtf(r2);
                float c2    = fmaf(0.5f * fabsf(tau), inv_r, 0.5f); // cos^2
                float cinv  = rsqrtf(c2);
                float cc    = c2 * cinv;                            // cos
                float st    = (tau < 0.0f) ? -apq : apq;            // sign(tau)*apq
                float ss    = st * inv_r * cinv;                    // sin
                float s2c   = 2.0f * st * inv_r;                    // sin(2phi) fold

                float napp = c2 * app + (1.0f - c2) * aqq - s2c * apq;
                AT(p, p) = napp;
                AT(q, q) = (app + aqq) - napp;
                AT(p, q) = 0.0f;

#pragma unroll
                for (int j = 0; j < 8; j++) {
                    if (j == p || j == q) continue;
                    float ajp = AT(j, p), ajq = AT(j, q);
                    AT(j, p) = cc * ajp - ss * ajq;
                    AT(j, q) = ss * ajp + cc * ajq;
                }

                // packed V column rotation
                ull cc2  = pk(cc, cc);
                ull ss2  = pk(ss, ss);
                ull nss2 = pk(-ss, -ss);
#pragma unroll
                for (int jp = 0; jp < 4; jp++) {
                    ull vp = Vp[p][jp], vq = Vp[q][jp];
                    Vp[p][jp] = fma2(nss2, vq, mul2(cc2, vp));
                    Vp[q][jp] = fma2(cc2,  vq, mul2(ss2, vp));
                }
            }
        }
    }

    float V[8][8];   // V[row][col]
#pragma unroll
    for (int c = 0; c < 8; c++)
#pragma unroll
        for (int jp = 0; jp < 4; jp++)
            upk(Vp[c][jp], V[2 * jp][c], V[2 * jp + 1][c]);

    float lam[8];
#pragma unroll
    for (int k = 0; k < 8; k++) lam[k] = fmaxf(AT(k, k), MIN_EIG);

    float W[8][8];
#pragma unroll
    for (int i = 0; i < 8; i++)
#pragma unroll
        for (int k = 0; k < 8; k++) W[i][k] = V[i][k] * lam[k];

    float pd[8][8];
#pragma unroll
    for (int i = 0; i < 8; i++) {
#pragma unroll
        for (int j = i; j < 8; j++) {
            float acc = 0.0f;
#pragma unroll
            for (int k = 0; k < 8; k++) acc = fmaf(W[i][k], V[j][k], acc);
            pd[i][j] = acc; pd[j][i] = acc;
        }
    }

    float* o = out_pd + (size_t)tok * 64;
#pragma unroll
    for (int i = 0; i < 8; i++) {
        ((float4*)o)[i * 2]     = make_float4(pd[i][0], pd[i][1], pd[i][2], pd[i][3]);
        ((float4*)o)[i * 2 + 1] = make_float4(pd[i][4], pd[i][5], pd[i][6], pd[i][7]);
    }
}

// ---------------------------------------------------------------------------
extern "C" void kernel_launch(void* const* d_in, const int* in_sizes, int n_in,
                              void* d_out, int out_size)
{
    // Identify inputs by element count (robust to metadata ordering):
    // x: 67108864, w_n: 64, b_n: 1, w_p: 2880, b_p: 9
    const float* x  = nullptr;
    const float* wn = nullptr;
    const float* bn = nullptr;
    const float* wp = nullptr;
    const float* bp = nullptr;
    for (int i = 0; i < n_in; i++) {
        switch (in_sizes[i]) {
            case 64:    wn = (const float*)d_in[i]; break;
            case 1:     bn = (const float*)d_in[i]; break;
            case 2880:  wp = (const float*)d_in[i]; break;
            case 9:     bp = (const float*)d_in[i]; break;
            default:    x  = (const float*)d_in[i]; break;
        }
    }

    float* out = (float*)d_out;
    float* loc = out;                                            // [B,1,H,FD]
    float* pd  = out + ((size_t)out_size - (size_t)NTOK * 64);   // [B,1,H,8,8]

    wprep_kernel<<<(OUTC * C_IN + 127) / 128, 128>>>(wn, wp);
    conv_kernel<<<NTOK / 128, 128>>>(x, bn, bp, loc);
    eigh_kernel<<<NTOK / 128, 128>>>(pd);
}